// round 14
// baseline (speedup 1.0000x reference)
#include <cuda_runtime.h>
#include <cstdint>
#include <math.h>

#define S_LEN  2048
#define DMODEL 1024
#define NH     16
#define DK     64
#define BATCH  4
#define M_TOT  (BATCH * S_LEN)   // 8192

// Scratch (static __device__ — no allocations allowed)
__device__ float g_Q[BATCH * NH * S_LEN * DK];
__device__ float g_K[BATCH * NH * S_LEN * DK];
__device__ float g_V[BATCH * NH * S_LEN * DK];
__device__ float g_rX0[(size_t)M_TOT * DMODEL];
__device__ float g_rX1[(size_t)M_TOT * DMODEL];
__device__ float g_rX2[(size_t)M_TOT * DMODEL];
__device__ float g_rW[4][(size_t)DMODEL * DMODEL];
__device__ float g_AO[(size_t)M_TOT * DMODEL];

// interleave perm within an 8-group: 0..7 -> 0,2,4,6,1,3,5,7
#define PERM8(x) (((x) & ~7) | (((x) & 3) << 1) | ((((x) >> 2)) & 1))

// ---------------------------------------------------------------------------
__device__ __forceinline__ float tf32_rn(float x) {
    uint32_t u;
    asm("cvt.rna.tf32.f32 %0, %1;" : "=r"(u) : "f"(x));
    return __uint_as_float(u);
}
__device__ __forceinline__ float ex2f(float x) {
    float y;
    asm("ex2.approx.f32 %0, %1;" : "=f"(y) : "f"(x));
    return y;
}
__device__ __forceinline__ uint32_t smem_u32(const void* p) {
    uint32_t a;
    asm("{ .reg .u64 t; cvta.to.shared.u64 t, %1; cvt.u32.u64 %0, t; }" : "=r"(a) : "l"(p));
    return a;
}
#define CP_ASYNC16(dst, src) \
    asm volatile("cp.async.cg.shared.global [%0], [%1], 16;" :: "r"(dst), "l"(src))
#define CP_COMMIT() asm volatile("cp.async.commit_group;" ::: "memory")
#define CP_WAIT1()  asm volatile("cp.async.wait_group 1;" ::: "memory")
#define CP_WAIT0()  asm volatile("cp.async.wait_group 0;" ::: "memory")

__device__ __forceinline__ void mma16n8k8(float* d, const float* a, const float* b) {
    asm volatile(
        "mma.sync.aligned.m16n8k8.row.col.f32.tf32.tf32.f32 "
        "{%0,%1,%2,%3}, {%4,%5,%6,%7}, {%8,%9}, {%0,%1,%2,%3};"
        : "+f"(d[0]), "+f"(d[1]), "+f"(d[2]), "+f"(d[3])
        : "r"(__float_as_uint(a[0])), "r"(__float_as_uint(a[1])),
          "r"(__float_as_uint(a[2])), "r"(__float_as_uint(a[3])),
          "r"(__float_as_uint(b[0])), "r"(__float_as_uint(b[1])));
}

// ---------------------------------------------------------------------------
// Prepass: round to tf32 (RN) and PERM8-interleave the k dimension.
// ---------------------------------------------------------------------------
__global__ void prep_kernel(const float* __restrict__ s0, const float* __restrict__ s1,
                            const float* __restrict__ s2, const float* __restrict__ s3,
                            float* __restrict__ d0, float* __restrict__ d1,
                            float* __restrict__ d2, float* __restrict__ d3, int n8)
{
    int i = blockIdx.x * blockDim.x + threadIdx.x;
    if (i >= n8) return;
    const int z = blockIdx.z;
    const float* s = (z == 0) ? s0 : (z == 1) ? s1 : (z == 2) ? s2 : s3;
    float*       d = (z == 0) ? d0 : (z == 1) ? d1 : (z == 2) ? d2 : d3;
    float4 u0 = *(const float4*)(s + (size_t)i * 8);
    float4 u1 = *(const float4*)(s + (size_t)i * 8 + 4);
    float4 o0 = make_float4(tf32_rn(u0.x), tf32_rn(u1.x), tf32_rn(u0.y), tf32_rn(u1.y));
    float4 o1 = make_float4(tf32_rn(u0.z), tf32_rn(u1.z), tf32_rn(u0.w), tf32_rn(u1.w));
    *(float4*)(d + (size_t)i * 8)     = o0;
    *(float4*)(d + (size_t)i * 8 + 4) = o1;
}

// ---------------------------------------------------------------------------
// Tensor-core GEMM v5: Y = X @ W^T + bias.  CTA 128x128, 8 warps (2m x 4n).
// BK=32 AND 3-stage cp.async ring with CP_WAIT1 -> 32 barriers total, 64 mma
// between barriers, 2 iterations (~1280 cyc) of load-latency cover.
// Ring safety: top barrier of iter j proves iter j-1 done = last reader of
// the buffer load(j+2) overwrites. Stride-36 smem: conflict-free LDS.64.
// Operands pre-rounded + k-PERM8'd -> zero cvt in the loop.
// mode 0: Q/K head scatter (d PERM8'd); mode 2: V transposed scatter;
// mode 1: plain [m][n] fp32.
// ---------------------------------------------------------------------------
#define GS 3
#define A_STR 36
#define GEMM_SMEM (GS * 128 * A_STR * 2 * 4)   // 110592 B

__global__ __launch_bounds__(256, 2) void gemm_mma_kernel(
    const float* __restrict__ X, const float* __restrict__ W,
    const float* __restrict__ bias, float* __restrict__ Y, int mode)
{
    extern __shared__ __align__(16) float gsm[];
    float (*As)[A_STR] = (float(*)[A_STR])gsm;
    float (*Bs)[A_STR] = (float(*)[A_STR])(gsm + GS * 128 * A_STR);
    const uint32_t sA = smem_u32(gsm);
    const uint32_t sB = sA + GS * 128 * A_STR * 4;

    const int tid  = threadIdx.x;
    const int lane = tid & 31;
    const int wid  = tid >> 5;
    const int g = lane >> 2;
    const int t = lane & 3;
    const int wm = (wid >> 2) * 64;
    const int wn = (wid & 3) * 32;
    const int m0 = blockIdx.y * 128;
    const int n0 = blockIdx.x * 128;

    // staging: 128 rows x 32 floats per matrix per stage; thread does 16 floats
    const int srow = tid >> 1;
    const int scol = (tid & 1) * 16;
    const float* Xp = X + (size_t)(m0 + srow) * DMODEL + scol;
    const float* Wp = W + (size_t)(n0 + srow) * DMODEL + scol;

    auto load_stage = [&](int j, int st) {
        const float* xp = Xp + j * 32;
        const float* wp = Wp + j * 32;
        const uint32_t da = sA + (uint32_t)(st * 128 * A_STR + srow * A_STR + scol) * 4;
        const uint32_t db = sB + (uint32_t)(st * 128 * A_STR + srow * A_STR + scol) * 4;
        #pragma unroll
        for (int i = 0; i < 4; i++) {
            CP_ASYNC16(da + i * 16, xp + i * 4);
            CP_ASYNC16(db + i * 16, wp + i * 4);
        }
        CP_COMMIT();
    };

    load_stage(0, 0);
    load_stage(1, 1);

    float acc[4][4][4] = {};

    const int NK = DMODEL / 32;                  // 32 k-steps
    for (int j = 0; j < NK; j++) {
        const int st = j % GS;
        if (j == NK - 1) { CP_WAIT0(); } else { CP_WAIT1(); }
        __syncthreads();   // stage j visible; all warps done with step j-1
        if (j + 2 < NK) load_stage(j + 2, (j + 2) % GS);

        const float (*Aj)[A_STR] = As + st * 128;
        const float (*Bj)[A_STR] = Bs + st * 128;

        #pragma unroll
        for (int kk = 0; kk < 32; kk += 8) {
            const int kc = kk + 2 * t;    // slot pair (orig t, orig t+4)
            float a[4][4], b[4][2];
            #pragma unroll
            for (int mi = 0; mi < 4; mi++) {
                const int mr = wm + mi * 16;
                float2 lo = *(const float2*)&Aj[mr + g    ][kc];
                float2 hi = *(const float2*)&Aj[mr + g + 8][kc];
                a[mi][0] = lo.x; a[mi][1] = hi.x; a[mi][2] = lo.y; a[mi][3] = hi.y;
            }
            #pragma unroll
            for (int ni = 0; ni < 4; ni++) {
                float2 bb = *(const float2*)&Bj[wn + ni * 8 + g][kc];
                b[ni][0] = bb.x; b[ni][1] = bb.y;
            }
            #pragma unroll
            for (int mi = 0; mi < 4; mi++)
                #pragma unroll
                for (int ni = 0; ni < 4; ni++)
                    mma16n8k8(acc[mi][ni], a[mi], b[ni]);
        }
    }

    #pragma unroll
    for (int mi = 0; mi < 4; mi++) {
        #pragma unroll
        for (int ni = 0; ni < 4; ni++) {
            const int n = n0 + wn + ni * 8 + 2 * t;
            const float bx = bias[n], by = bias[n + 1];
            #pragma unroll
            for (int half = 0; half < 2; half++) {
                const int m = m0 + wm + mi * 16 + g + half * 8;
                float ox = acc[mi][ni][half * 2 + 0] + bx;
                float oy = acc[mi][ni][half * 2 + 1] + by;
                if (mode == 1) {
                    *(float2*)&Y[(size_t)m * DMODEL + n] = make_float2(ox, oy);
                } else {
                    ox = tf32_rn(ox);
                    oy = tf32_rn(oy);
                    const int bb = m >> 11;
                    const int s  = m & 2047;
                    const int h  = n >> 6;
                    if (mode == 0) {
                        const int d0 = n & 63;
                        size_t base = ((size_t)(bb * NH + h) * S_LEN + s) * DK;
                        Y[base + PERM8(d0)]     = ox;
                        Y[base + PERM8(d0 + 1)] = oy;
                    } else {   // mode 2: V transposed [b,h,d,s], s permuted
                        const int sp = PERM8(s);
                        size_t base = ((size_t)(bb * NH + h) * DK + (size_t)(n & 63)) * S_LEN;
                        Y[base + sp]         = ox;
                        Y[base + S_LEN + sp] = oy;
                    }
                }
            }
        }
    }
}

// ---------------------------------------------------------------------------
// Tensor-core flash attention v6 (unchanged from R13 — it improved).
// CTA = one (b,h) x 128 q-rows; 8 warps x 16 q-rows; kv-tiles of 64.
// 3-stage K/V ring, ONE barrier per tile. Key-interleave: score acc IS the
// PV A-fragment. All B-frags LDS.64, stride 72 conflict-free. exp2 softmax.
// ---------------------------------------------------------------------------
#define NT     (S_LEN / 64)
#define K_STR  72
#define V_STR  72
#define NSTG   3
#define ATT_SMEM ((NSTG*64*K_STR + NSTG*64*V_STR) * 4)   // 110592 B

__global__ __launch_bounds__(256, 2) void attn_mma_kernel(float* __restrict__ AO)
{
    extern __shared__ __align__(16) float sm[];
    float (*Kb)[K_STR] = (float(*)[K_STR])sm;
    float (*Vb)[V_STR] = (float(*)[V_STR])(sm + NSTG*64*K_STR);
    const uint32_t skb = smem_u32(sm);
    const uint32_t svb = skb + NSTG*64*K_STR*4;

    const int tid  = threadIdx.x;
    const int lane = tid & 31;
    const int wid  = tid >> 5;          // 0..7
    const int g = lane >> 2;
    const int t = lane & 3;
    const int q0 = blockIdx.x * 128;
    const int bh = blockIdx.y;
    const int mr = wid * 16;

    const float* Qg = g_Q + (size_t)bh * S_LEN * DK;
    const float* Kg = g_K + (size_t)bh * S_LEN * DK;
    const float* Vg = g_V + (size_t)bh * DK * S_LEN;

    const int lrow = tid >> 2;          // 0..63
    const int lcb  = (tid & 3) * 16;
    const int krow = PERM8(lrow);
    auto load_tile = [&](int j, int buf) {
        const float* kp = Kg + (size_t)(j * 64 + lrow) * DK + lcb;
        const float* vp = Vg + (size_t)lrow * S_LEN + j * 64 + lcb;
        const uint32_t kd = skb + (uint32_t)(buf * 64 * K_STR + krow * K_STR + lcb) * 4;
        const uint32_t vd = svb + (uint32_t)(buf * 64 * V_STR + lrow * V_STR + lcb) * 4;
        #pragma unroll
        for (int i = 0; i < 4; i++) {
            CP_ASYNC16(kd + i * 16, kp + i * 4);
            CP_ASYNC16(vd + i * 16, vp + i * 4);
        }
        CP_COMMIT();
    };

    load_tile(0, 0);
    load_tile(1, 1);

    // Q fragments (d-permuted gmem -> LDG.64), scaled by log2e/8, re-rounded.
    const float SC = 0.125f * 1.4426950408889634f;
    float qf[8][4];
    {
        const float* r0 = Qg + (size_t)(q0 + mr + g)     * DK;
        const float* r1 = Qg + (size_t)(q0 + mr + g + 8) * DK;
        #pragma unroll
        for (int kk8 = 0; kk8 < 8; kk8++) {
            const int c = kk8 * 8 + 2 * t;
            float2 u0 = *(const float2*)(r0 + c);
            float2 u1 = *(const float2*)(r1 + c);
            qf[kk8][0] = tf32_rn(SC * u0.x);
            qf[kk8][1] = tf32_rn(SC * u1.x);
            qf[kk8][2] = tf32_rn(SC * u0.y);
            qf[kk8][3] = tf32_rn(SC * u1.y);
        }
    }

    float oacc[8][4] = {};
    float mrow[2] = {-1e30f, -1e30f};
    float lrow2[2] = {0.f, 0.f};
    const uint32_t FULL = 0xffffffffu;

    for (int j = 0; j < NT; j++) {
        const int buf = j % NSTG;
        if (j == NT - 1) { CP_WAIT0(); } else { CP_WAIT1(); }
        __syncthreads();   // tile j visible; all warps done with tile j-1

        const float (*Ks)[K_STR] = Kb + buf * 64;
        const float (*Vs)[V_STR] = Vb + buf * 64;

        // scores (log2 domain)
        float sacc[8][4] = {};
        #pragma unroll
        for (int kk8 = 0; kk8 < 8; kk8++) {
            const int kc = kk8 * 8 + 2 * t;
            #pragma unroll
            for (int ni = 0; ni < 8; ni++) {
                float2 kb2 = *(const float2*)&Ks[ni * 8 + g][kc];
                float b2[2] = {kb2.x, kb2.y};
                mma16n8k8(sacc[ni], qf[kk8], b2);
            }
        }

        // online softmax, base-2
        #pragma unroll
        for (int hf = 0; hf < 2; hf++) {
            float mx = -1e30f;
            #pragma unroll
            for (int ni = 0; ni < 8; ni++)
                mx = fmaxf(mx, fmaxf(sacc[ni][hf * 2], sacc[ni][hf * 2 + 1]));
            mx = fmaxf(mx, __shfl_xor_sync(FULL, mx, 1));
            mx = fmaxf(mx, __shfl_xor_sync(FULL, mx, 2));
            const float mnew = fmaxf(mrow[hf], mx);
            const float alpha = ex2f(mrow[hf] - mnew);
            mrow[hf] = mnew;
            float sum = 0.f;
            #pragma unroll
            for (int ni = 0; ni < 8; ni++) {
                float p0 = ex2f(sacc[ni][hf * 2 + 0] - mnew);
                float p1 = ex2f(sacc[ni][hf * 2 + 1] - mnew);
                sacc[ni][hf * 2 + 0] = p0;
                sacc[ni][hf * 2 + 1] = p1;
                sum += p0 + p1;
            }
            sum += __shfl_xor_sync(FULL, sum, 1);
            sum += __shfl_xor_sync(FULL, sum, 2);
            lrow2[hf] = lrow2[hf] * alpha + sum;
            #pragma unroll
            for (int ni = 0; ni < 8; ni++) {
                oacc[ni][hf * 2 + 0] *= alpha;
                oacc[ni][hf * 2 + 1] *= alpha;
            }
        }

        // O += P @ V (score acc IS the A-fragment after key interleave)
        #pragma unroll
        for (int kk8 = 0; kk8 < 8; kk8++) {
            const int kc = kk8 * 8 + 2 * t;
            float a[4];
            a[0] = tf32_rn(sacc[kk8][0]);
            a[1] = tf32_rn(sacc[kk8][2]);
            a[2] = tf32_rn(sacc[kk8][1]);
            a[3] = tf32_rn(sacc[kk8][3]);
            #pragma unroll
            for (int ni = 0; ni < 8; ni++) {
                float2 vb2 = *(const float2*)&Vs[ni * 8 + g][kc];
                float b2[2] = {vb2.x, vb2.y};
                mma16n8k8(oacc[ni], a, b2);
            }
        }

        // no trailing barrier (ring reuse distance 3)
        if (j + 2 < NT) load_tile(j + 2, (j + 2) % NSTG);
    }

    // epilogue: AO[b*S+s][h*64 + PERM8(d)] = tf32_rn(O / l)
    const int h = bh & (NH - 1);
    const int b = bh >> 4;
    const float inv0 = 1.0f / lrow2[0];
    const float inv1 = 1.0f / lrow2[1];
    const int r0 = q0 + mr + g;
    const int p0 = PERM8(2 * t);
    const int p1 = PERM8(2 * t + 1);
    #pragma unroll
    for (int ni = 0; ni < 8; ni++) {
        const int db = ni * 8;
        size_t i0 = ((size_t)(b * S_LEN + r0    )) * DMODEL + (size_t)(h * DK + db);
        size_t i1 = ((size_t)(b * S_LEN + r0 + 8)) * DMODEL + (size_t)(h * DK + db);
        AO[i0 + p0] = tf32_rn(oacc[ni][0] * inv0);
        AO[i0 + p1] = tf32_rn(oacc[ni][1] * inv0);
        AO[i1 + p0] = tf32_rn(oacc[ni][2] * inv1);
        AO[i1 + p1] = tf32_rn(oacc[ni][3] * inv1);
    }
}

// ---------------------------------------------------------------------------
extern "C" void kernel_launch(void* const* d_in, const int* in_sizes, int n_in,
                              void* d_out, int out_size)
{
    (void)in_sizes; (void)n_in; (void)out_size;
    const float* q  = (const float*)d_in[0];
    const float* k  = (const float*)d_in[1];
    const float* v  = (const float*)d_in[2];
    const float* Wq = (const float*)d_in[3];
    const float* bq = (const float*)d_in[4];
    const float* Wk = (const float*)d_in[5];
    const float* bk = (const float*)d_in[6];
    const float* Wv = (const float*)d_in[7];
    const float* bv = (const float*)d_in[8];
    const float* Wo = (const float*)d_in[9];
    const float* bo = (const float*)d_in[10];
    float* out = (float*)d_out;

    float *Qp, *Kp, *Vp, *AOp, *X0, *X1, *X2, *Wr;
    cudaGetSymbolAddress((void**)&Qp,  g_Q);
    cudaGetSymbolAddress((void**)&Kp,  g_K);
    cudaGetSymbolAddress((void**)&Vp,  g_V);
    cudaGetSymbolAddress((void**)&AOp, g_AO);
    cudaGetSymbolAddress((void**)&X0,  g_rX0);
    cudaGetSymbolAddress((void**)&X1,  g_rX1);
    cudaGetSymbolAddress((void**)&X2,  g_rX2);
    cudaGetSymbolAddress((void**)&Wr,  g_rW);
    float* W0 = Wr;
    float* W1 = Wr + (size_t)DMODEL * DMODEL;
    float* W2 = Wr + 2 * (size_t)DMODEL * DMODEL;
    float* W3 = Wr + 3 * (size_t)DMODEL * DMODEL;

    cudaFuncSetAttribute(gemm_mma_kernel,
                         cudaFuncAttributeMaxDynamicSharedMemorySize, GEMM_SMEM);
    cudaFuncSetAttribute(attn_mma_kernel,
                         cudaFuncAttributeMaxDynamicSharedMemorySize, ATT_SMEM);

    // prepass: round + k-permute activations (z=3) and weights (z=4)
    const int nX8 = (M_TOT * DMODEL) / 8;
    const int nW8 = (DMODEL * DMODEL) / 8;
    prep_kernel<<<dim3((nX8 + 255) / 256, 1, 3), 256>>>(q, k, v, nullptr,
                                                        X0, X1, X2, nullptr, nX8);
    prep_kernel<<<dim3((nW8 + 255) / 256, 1, 4), 256>>>(Wq, Wk, Wv, Wo,
                                                        W0, W1, W2, W3, nW8);

    dim3 ggrid(DMODEL / 128, M_TOT / 128);   // (8, 64)
    gemm_mma_kernel<<<ggrid, 256, GEMM_SMEM>>>(X0, W0, bq, Qp, 0);
    gemm_mma_kernel<<<ggrid, 256, GEMM_SMEM>>>(X1, W1, bk, Kp, 0);
    gemm_mma_kernel<<<ggrid, 256, GEMM_SMEM>>>(X2, W2, bv, Vp, 2);

    attn_mma_kernel<<<dim3(S_LEN / 128, BATCH * NH), 256, ATT_SMEM>>>(AOp);

    gemm_mma_kernel<<<ggrid, 256, GEMM_SMEM>>>(AOp, W3, bo, out, 1);
}

// round 17
// speedup vs baseline: 1.1732x; 1.1732x over previous
#include <cuda_runtime.h>
#include <cstdint>
#include <math.h>

#define S_LEN  2048
#define DMODEL 1024
#define NH     16
#define DK     64
#define BATCH  4
#define M_TOT  (BATCH * S_LEN)   // 8192

// Scratch (static __device__ — no allocations allowed)
__device__ float g_Q[BATCH * NH * S_LEN * DK];
__device__ float g_K[BATCH * NH * S_LEN * DK];
__device__ float g_V[BATCH * NH * S_LEN * DK];
__device__ float g_rX0[(size_t)M_TOT * DMODEL];
__device__ float g_rX1[(size_t)M_TOT * DMODEL];
__device__ float g_rX2[(size_t)M_TOT * DMODEL];
__device__ float g_rW[4][(size_t)DMODEL * DMODEL];
__device__ float g_AO[(size_t)M_TOT * DMODEL];

// interleave perm within an 8-group: 0..7 -> 0,2,4,6,1,3,5,7
#define PERM8(x) (((x) & ~7) | (((x) & 3) << 1) | ((((x) >> 2)) & 1))

// ---------------------------------------------------------------------------
__device__ __forceinline__ float tf32_rn(float x) {
    uint32_t u;
    asm("cvt.rna.tf32.f32 %0, %1;" : "=r"(u) : "f"(x));
    return __uint_as_float(u);
}
__device__ __forceinline__ float ex2f(float x) {
    float y;
    asm("ex2.approx.f32 %0, %1;" : "=f"(y) : "f"(x));
    return y;
}
__device__ __forceinline__ uint32_t smem_u32(const void* p) {
    uint32_t a;
    asm("{ .reg .u64 t; cvta.to.shared.u64 t, %1; cvt.u32.u64 %0, t; }" : "=r"(a) : "l"(p));
    return a;
}
#define CP_ASYNC16(dst, src) \
    asm volatile("cp.async.cg.shared.global [%0], [%1], 16;" :: "r"(dst), "l"(src))
#define CP_COMMIT() asm volatile("cp.async.commit_group;" ::: "memory")
#define CP_WAIT1()  asm volatile("cp.async.wait_group 1;" ::: "memory")
#define CP_WAIT0()  asm volatile("cp.async.wait_group 0;" ::: "memory")

__device__ __forceinline__ void mma16n8k8(float* d, const float* a, const float* b) {
    asm volatile(
        "mma.sync.aligned.m16n8k8.row.col.f32.tf32.tf32.f32 "
        "{%0,%1,%2,%3}, {%4,%5,%6,%7}, {%8,%9}, {%0,%1,%2,%3};"
        : "+f"(d[0]), "+f"(d[1]), "+f"(d[2]), "+f"(d[3])
        : "r"(__float_as_uint(a[0])), "r"(__float_as_uint(a[1])),
          "r"(__float_as_uint(a[2])), "r"(__float_as_uint(a[3])),
          "r"(__float_as_uint(b[0])), "r"(__float_as_uint(b[1])));
}

// ---------------------------------------------------------------------------
// Prepass: round to tf32 (RN) and PERM8-interleave the k dimension.
// ---------------------------------------------------------------------------
__global__ void prep_kernel(const float* __restrict__ s0, const float* __restrict__ s1,
                            const float* __restrict__ s2, const float* __restrict__ s3,
                            float* __restrict__ d0, float* __restrict__ d1,
                            float* __restrict__ d2, float* __restrict__ d3, int n8)
{
    int i = blockIdx.x * blockDim.x + threadIdx.x;
    if (i >= n8) return;
    const int z = blockIdx.z;
    const float* s = (z == 0) ? s0 : (z == 1) ? s1 : (z == 2) ? s2 : s3;
    float*       d = (z == 0) ? d0 : (z == 1) ? d1 : (z == 2) ? d2 : d3;
    float4 u0 = *(const float4*)(s + (size_t)i * 8);
    float4 u1 = *(const float4*)(s + (size_t)i * 8 + 4);
    float4 o0 = make_float4(tf32_rn(u0.x), tf32_rn(u1.x), tf32_rn(u0.y), tf32_rn(u1.y));
    float4 o1 = make_float4(tf32_rn(u0.z), tf32_rn(u1.z), tf32_rn(u0.w), tf32_rn(u1.w));
    *(float4*)(d + (size_t)i * 8)     = o0;
    *(float4*)(d + (size_t)i * 8 + 4) = o1;
}

// ---------------------------------------------------------------------------
// Tensor-core GEMM core (R12-verified config): CTA 128x128, 8 warps (2m x 4n).
// BK=16, 3-stage cp.async ring, CP_WAIT1, one barrier per k-step.
// Stride-24 smem: conflict-free LDS.64 frag loads per half-warp.
// Operands pre-rounded + k-PERM8'd -> zero cvt in the loop.
// Epilogue mode: 0 = Q/K head scatter (d PERM8'd), 2 = V transposed scatter,
//                1 = plain [m][n] fp32.
// ---------------------------------------------------------------------------
#define GS 3
#define A_STR 24
#define GEMM_SMEM (GS * 128 * A_STR * 2 * 4)   // 73728 B

__device__ __forceinline__ void gemm_core(
    const float* __restrict__ X, const float* __restrict__ W,
    const float* __restrict__ bias, float* __restrict__ Y, int mode)
{
    extern __shared__ __align__(16) float gsm[];
    float (*As)[A_STR] = (float(*)[A_STR])gsm;
    float (*Bs)[A_STR] = (float(*)[A_STR])(gsm + GS * 128 * A_STR);
    const uint32_t sA = smem_u32(gsm);
    const uint32_t sB = sA + GS * 128 * A_STR * 4;

    const int tid  = threadIdx.x;
    const int lane = tid & 31;
    const int wid  = tid >> 5;
    const int g = lane >> 2;
    const int t = lane & 3;
    const int wm = (wid >> 2) * 64;
    const int wn = (wid & 3) * 32;
    const int m0 = blockIdx.y * 128;
    const int n0 = blockIdx.x * 128;

    const int srow = tid >> 1;
    const int scol = (tid & 1) * 8;
    const float* Xp = X + (size_t)(m0 + srow) * DMODEL + scol;
    const float* Wp = W + (size_t)(n0 + srow) * DMODEL + scol;

    auto load_stage = [&](int j, int st) {
        const float* xp = Xp + j * 16;
        const float* wp = Wp + j * 16;
        const uint32_t da = sA + (uint32_t)(st * 128 * A_STR + srow * A_STR + scol) * 4;
        const uint32_t db = sB + (uint32_t)(st * 128 * A_STR + srow * A_STR + scol) * 4;
        CP_ASYNC16(da, xp);      CP_ASYNC16(da + 16, xp + 4);
        CP_ASYNC16(db, wp);      CP_ASYNC16(db + 16, wp + 4);
        CP_COMMIT();
    };

    load_stage(0, 0);
    load_stage(1, 1);

    float acc[4][4][4] = {};

    for (int j = 0; j < DMODEL / 16; j++) {
        const int st = j % GS;
        if (j == DMODEL / 16 - 1) { CP_WAIT0(); } else { CP_WAIT1(); }
        __syncthreads();
        if (j + 2 < DMODEL / 16) load_stage(j + 2, (j + 2) % GS);

        const float (*Aj)[A_STR] = As + st * 128;
        const float (*Bj)[A_STR] = Bs + st * 128;

        #pragma unroll
        for (int kk = 0; kk < 16; kk += 8) {
            const int kc = kk + 2 * t;    // slot pair (orig t, orig t+4)
            float a[4][4], b[4][2];
            #pragma unroll
            for (int mi = 0; mi < 4; mi++) {
                const int mr = wm + mi * 16;
                float2 lo = *(const float2*)&Aj[mr + g    ][kc];
                float2 hi = *(const float2*)&Aj[mr + g + 8][kc];
                a[mi][0] = lo.x; a[mi][1] = hi.x; a[mi][2] = lo.y; a[mi][3] = hi.y;
            }
            #pragma unroll
            for (int ni = 0; ni < 4; ni++) {
                float2 bb = *(const float2*)&Bj[wn + ni * 8 + g][kc];
                b[ni][0] = bb.x; b[ni][1] = bb.y;
            }
            #pragma unroll
            for (int mi = 0; mi < 4; mi++)
                #pragma unroll
                for (int ni = 0; ni < 4; ni++)
                    mma16n8k8(acc[mi][ni], a[mi], b[ni]);
        }
    }

    #pragma unroll
    for (int mi = 0; mi < 4; mi++) {
        #pragma unroll
        for (int ni = 0; ni < 4; ni++) {
            const int n = n0 + wn + ni * 8 + 2 * t;
            const float bx = bias[n], by = bias[n + 1];
            #pragma unroll
            for (int half = 0; half < 2; half++) {
                const int m = m0 + wm + mi * 16 + g + half * 8;
                float ox = acc[mi][ni][half * 2 + 0] + bx;
                float oy = acc[mi][ni][half * 2 + 1] + by;
                if (mode == 1) {
                    *(float2*)&Y[(size_t)m * DMODEL + n] = make_float2(ox, oy);
                } else {
                    ox = tf32_rn(ox);
                    oy = tf32_rn(oy);
                    const int bb = m >> 11;
                    const int s  = m & 2047;
                    const int h  = n >> 6;
                    if (mode == 0) {
                        const int d0 = n & 63;
                        size_t base = ((size_t)(bb * NH + h) * S_LEN + s) * DK;
                        Y[base + PERM8(d0)]     = ox;
                        Y[base + PERM8(d0 + 1)] = oy;
                    } else {   // mode 2: V transposed [b,h,d,s], s permuted
                        const int sp = PERM8(s);
                        size_t base = ((size_t)(bb * NH + h) * DK + (size_t)(n & 63)) * S_LEN;
                        Y[base + sp]         = ox;
                        Y[base + S_LEN + sp] = oy;
                    }
                }
            }
        }
    }
}

// Fused Q/K/V projection: blockIdx.z selects the GEMM (0=Q, 1=K, 2=V).
// 1536 CTAs in one launch -> one tail wave instead of three.
__global__ __launch_bounds__(256, 2) void gemm_qkv_kernel(
    const float* __restrict__ X0, const float* __restrict__ X1, const float* __restrict__ X2,
    const float* __restrict__ W0, const float* __restrict__ W1, const float* __restrict__ W2,
    const float* __restrict__ b0, const float* __restrict__ b1, const float* __restrict__ b2,
    float* __restrict__ Y0, float* __restrict__ Y1, float* __restrict__ Y2)
{
    const int z = blockIdx.z;
    const float* X = (z == 0) ? X0 : (z == 1) ? X1 : X2;
    const float* W = (z == 0) ? W0 : (z == 1) ? W1 : W2;
    const float* bias = (z == 0) ? b0 : (z == 1) ? b1 : b2;
    float* Y = (z == 0) ? Y0 : (z == 1) ? Y1 : Y2;
    gemm_core(X, W, bias, Y, (z == 2) ? 2 : 0);
}

// Single GEMM (used for the output projection, mode 1).
__global__ __launch_bounds__(256, 2) void gemm_mma_kernel(
    const float* __restrict__ X, const float* __restrict__ W,
    const float* __restrict__ bias, float* __restrict__ Y, int mode)
{
    gemm_core(X, W, bias, Y, mode);
}

// ---------------------------------------------------------------------------
// Tensor-core flash attention v6 (unchanged — verified best).
// CTA = one (b,h) x 128 q-rows; 8 warps x 16 q-rows; kv-tiles of 64.
// 3-stage K/V ring, ONE barrier per tile. Key-interleave: score acc IS the
// PV A-fragment. All B-frags LDS.64, stride 72 conflict-free. exp2 softmax.
// ---------------------------------------------------------------------------
#define NT     (S_LEN / 64)
#define K_STR  72
#define V_STR  72
#define NSTG   3
#define ATT_SMEM ((NSTG*64*K_STR + NSTG*64*V_STR) * 4)   // 110592 B

__global__ __launch_bounds__(256, 2) void attn_mma_kernel(float* __restrict__ AO)
{
    extern __shared__ __align__(16) float sm[];
    float (*Kb)[K_STR] = (float(*)[K_STR])sm;
    float (*Vb)[V_STR] = (float(*)[V_STR])(sm + NSTG*64*K_STR);
    const uint32_t skb = smem_u32(sm);
    const uint32_t svb = skb + NSTG*64*K_STR*4;

    const int tid  = threadIdx.x;
    const int lane = tid & 31;
    const int wid  = tid >> 5;          // 0..7
    const int g = lane >> 2;
    const int t = lane & 3;
    const int q0 = blockIdx.x * 128;
    const int bh = blockIdx.y;
    const int mr = wid * 16;

    const float* Qg = g_Q + (size_t)bh * S_LEN * DK;
    const float* Kg = g_K + (size_t)bh * S_LEN * DK;
    const float* Vg = g_V + (size_t)bh * DK * S_LEN;

    const int lrow = tid >> 2;          // 0..63
    const int lcb  = (tid & 3) * 16;
    const int krow = PERM8(lrow);
    auto load_tile = [&](int j, int buf) {
        const float* kp = Kg + (size_t)(j * 64 + lrow) * DK + lcb;
        const float* vp = Vg + (size_t)lrow * S_LEN + j * 64 + lcb;
        const uint32_t kd = skb + (uint32_t)(buf * 64 * K_STR + krow * K_STR + lcb) * 4;
        const uint32_t vd = svb + (uint32_t)(buf * 64 * V_STR + lrow * V_STR + lcb) * 4;
        #pragma unroll
        for (int i = 0; i < 4; i++) {
            CP_ASYNC16(kd + i * 16, kp + i * 4);
            CP_ASYNC16(vd + i * 16, vp + i * 4);
        }
        CP_COMMIT();
    };

    load_tile(0, 0);
    load_tile(1, 1);

    // Q fragments (d-permuted gmem -> LDG.64), scaled by log2e/8, re-rounded.
    const float SC = 0.125f * 1.4426950408889634f;
    float qf[8][4];
    {
        const float* r0 = Qg + (size_t)(q0 + mr + g)     * DK;
        const float* r1 = Qg + (size_t)(q0 + mr + g + 8) * DK;
        #pragma unroll
        for (int kk8 = 0; kk8 < 8; kk8++) {
            const int c = kk8 * 8 + 2 * t;
            float2 u0 = *(const float2*)(r0 + c);
            float2 u1 = *(const float2*)(r1 + c);
            qf[kk8][0] = tf32_rn(SC * u0.x);
            qf[kk8][1] = tf32_rn(SC * u1.x);
            qf[kk8][2] = tf32_rn(SC * u0.y);
            qf[kk8][3] = tf32_rn(SC * u1.y);
        }
    }

    float oacc[8][4] = {};
    float mrow[2] = {-1e30f, -1e30f};
    float lrow2[2] = {0.f, 0.f};
    const uint32_t FULL = 0xffffffffu;

    for (int j = 0; j < NT; j++) {
        const int buf = j % NSTG;
        if (j == NT - 1) { CP_WAIT0(); } else { CP_WAIT1(); }
        __syncthreads();   // tile j visible; all warps done with tile j-1

        const float (*Ks)[K_STR] = Kb + buf * 64;
        const float (*Vs)[V_STR] = Vb + buf * 64;

        // scores (log2 domain)
        float sacc[8][4] = {};
        #pragma unroll
        for (int kk8 = 0; kk8 < 8; kk8++) {
            const int kc = kk8 * 8 + 2 * t;
            #pragma unroll
            for (int ni = 0; ni < 8; ni++) {
                float2 kb2 = *(const float2*)&Ks[ni * 8 + g][kc];
                float b2[2] = {kb2.x, kb2.y};
                mma16n8k8(sacc[ni], qf[kk8], b2);
            }
        }

        // online softmax, base-2
        #pragma unroll
        for (int hf = 0; hf < 2; hf++) {
            float mx = -1e30f;
            #pragma unroll
            for (int ni = 0; ni < 8; ni++)
                mx = fmaxf(mx, fmaxf(sacc[ni][hf * 2], sacc[ni][hf * 2 + 1]));
            mx = fmaxf(mx, __shfl_xor_sync(FULL, mx, 1));
            mx = fmaxf(mx, __shfl_xor_sync(FULL, mx, 2));
            const float mnew = fmaxf(mrow[hf], mx);
            const float alpha = ex2f(mrow[hf] - mnew);
            mrow[hf] = mnew;
            float sum = 0.f;
            #pragma unroll
            for (int ni = 0; ni < 8; ni++) {
                float p0 = ex2f(sacc[ni][hf * 2 + 0] - mnew);
                float p1 = ex2f(sacc[ni][hf * 2 + 1] - mnew);
                sacc[ni][hf * 2 + 0] = p0;
                sacc[ni][hf * 2 + 1] = p1;
                sum += p0 + p1;
            }
            sum += __shfl_xor_sync(FULL, sum, 1);
            sum += __shfl_xor_sync(FULL, sum, 2);
            lrow2[hf] = lrow2[hf] * alpha + sum;
            #pragma unroll
            for (int ni = 0; ni < 8; ni++) {
                oacc[ni][hf * 2 + 0] *= alpha;
                oacc[ni][hf * 2 + 1] *= alpha;
            }
        }

        // O += P @ V (score acc IS the A-fragment after key interleave)
        #pragma unroll
        for (int kk8 = 0; kk8 < 8; kk8++) {
            const int kc = kk8 * 8 + 2 * t;
            float a[4];
            a[0] = tf32_rn(sacc[kk8][0]);
            a[1] = tf32_rn(sacc[kk8][2]);
            a[2] = tf32_rn(sacc[kk8][1]);
            a[3] = tf32_rn(sacc[kk8][3]);
            #pragma unroll
            for (int ni = 0; ni < 8; ni++) {
                float2 vb2 = *(const float2*)&Vs[ni * 8 + g][kc];
                float b2[2] = {vb2.x, vb2.y};
                mma16n8k8(oacc[ni], a, b2);
            }
        }

        // no trailing barrier (ring reuse distance 3)
        if (j + 2 < NT) load_tile(j + 2, (j + 2) % NSTG);
    }

    // epilogue: AO[b*S+s][h*64 + PERM8(d)] = tf32_rn(O / l)
    const int h = bh & (NH - 1);
    const int b = bh >> 4;
    const float inv0 = 1.0f / lrow2[0];
    const float inv1 = 1.0f / lrow2[1];
    const int r0 = q0 + mr + g;
    const int p0 = PERM8(2 * t);
    const int p1 = PERM8(2 * t + 1);
    #pragma unroll
    for (int ni = 0; ni < 8; ni++) {
        const int db = ni * 8;
        size_t i0 = ((size_t)(b * S_LEN + r0    )) * DMODEL + (size_t)(h * DK + db);
        size_t i1 = ((size_t)(b * S_LEN + r0 + 8)) * DMODEL + (size_t)(h * DK + db);
        AO[i0 + p0] = tf32_rn(oacc[ni][0] * inv0);
        AO[i0 + p1] = tf32_rn(oacc[ni][1] * inv0);
        AO[i1 + p0] = tf32_rn(oacc[ni][2] * inv1);
        AO[i1 + p1] = tf32_rn(oacc[ni][3] * inv1);
    }
}

// ---------------------------------------------------------------------------
extern "C" void kernel_launch(void* const* d_in, const int* in_sizes, int n_in,
                              void* d_out, int out_size)
{
    (void)in_sizes; (void)n_in; (void)out_size;
    const float* q  = (const float*)d_in[0];
    const float* k  = (const float*)d_in[1];
    const float* v  = (const float*)d_in[2];
    const float* Wq = (const float*)d_in[3];
    const float* bq = (const float*)d_in[4];
    const float* Wk = (const float*)d_in[5];
    const float* bk = (const float*)d_in[6];
    const float* Wv = (const float*)d_in[7];
    const float* bv = (const float*)d_in[8];
    const float* Wo = (const float*)d_in[9];
    const float* bo = (const float*)d_in[10];
    float* out = (float*)d_out;

    float *Qp, *Kp, *Vp, *AOp, *X0, *X1, *X2, *Wr;
    cudaGetSymbolAddress((void**)&Qp,  g_Q);
    cudaGetSymbolAddress((void**)&Kp,  g_K);
    cudaGetSymbolAddress((void**)&Vp,  g_V);
    cudaGetSymbolAddress((void**)&AOp, g_AO);
    cudaGetSymbolAddress((void**)&X0,  g_rX0);
    cudaGetSymbolAddress((void**)&X1,  g_rX1);
    cudaGetSymbolAddress((void**)&X2,  g_rX2);
    cudaGetSymbolAddress((void**)&Wr,  g_rW);
    float* W0 = Wr;
    float* W1 = Wr + (size_t)DMODEL * DMODEL;
    float* W2 = Wr + 2 * (size_t)DMODEL * DMODEL;
    float* W3 = Wr + 3 * (size_t)DMODEL * DMODEL;

    cudaFuncSetAttribute(gemm_qkv_kernel,
                         cudaFuncAttributeMaxDynamicSharedMemorySize, GEMM_SMEM);
    cudaFuncSetAttribute(gemm_mma_kernel,
                         cudaFuncAttributeMaxDynamicSharedMemorySize, GEMM_SMEM);
    cudaFuncSetAttribute(attn_mma_kernel,
                         cudaFuncAttributeMaxDynamicSharedMemorySize, ATT_SMEM);

    // prepass: round + k-permute activations (z=3) and weights (z=4)
    const int nX8 = (M_TOT * DMODEL) / 8;
    const int nW8 = (DMODEL * DMODEL) / 8;
    prep_kernel<<<dim3((nX8 + 255) / 256, 1, 3), 256>>>(q, k, v, nullptr,
                                                        X0, X1, X2, nullptr, nX8);
    prep_kernel<<<dim3((nW8 + 255) / 256, 1, 4), 256>>>(Wq, Wk, Wv, Wo,
                                                        W0, W1, W2, W3, nW8);

    // fused Q/K/V projection: one launch, 1536 CTAs, single tail wave
    gemm_qkv_kernel<<<dim3(DMODEL / 128, M_TOT / 128, 3), 256, GEMM_SMEM>>>(
        X0, X1, X2, W0, W1, W2, bq, bk, bv, Qp, Kp, Vp);

    attn_mma_kernel<<<dim3(S_LEN / 128, BATCH * NH), 256, ATT_SMEM>>>(AOp);

    gemm_mma_kernel<<<dim3(DMODEL / 128, M_TOT / 128), 256, GEMM_SMEM>>>(
        AOp, W3, bo, out, 1);
}